// round 14
// baseline (speedup 1.0000x reference)
#include <cuda_runtime.h>
#include <cuda_fp16.h>
#include <math.h>
#include <stdint.h>

#define TOKENS 4096      // 2 * 2048
#define HID    1024
#define FFDIM  4096
#define SEQ    2048
#define NHEADS 16
#define DK     64
#define QVN    2048      // fused Q|V projection width

// ---------------- scratch (device globals; no allocs allowed) ----------------
__device__ float  g_x1  [TOKENS * HID];
__device__ __half g_qv16[(size_t)TOKENS * QVN];
__device__ __half g_ln16[TOKENS * HID];
__device__ __half g_ctx16[TOKENS * HID];
__device__ __half g_h116[(size_t)TOKENS * FFDIM];
// fp16 weights
__device__ __half g_wqv16[(size_t)HID * QVN];   // [k][ Wq | Wv ]
__device__ __half g_wo16[HID * HID];
__device__ __half g_w116[(size_t)HID * FFDIM];
__device__ __half g_w216[(size_t)HID * FFDIM];
__device__ float  g_bqv [QVN];

// ---------------- fused weight convert: Wo + W1 + W2 in ONE launch ----------
// blocks [0, NB_H): Wo ; [NB_H, NB_H+NB_F): W1 ; [NB_H+NB_F, NB_H+2*NB_F): W2
#define NB_H (HID * HID / 1024)
#define NB_F (HID * FFDIM / 1024)
__global__ __launch_bounds__(256) void cvt_all(
    const float* __restrict__ Wo, const float* __restrict__ W1,
    const float* __restrict__ W2,
    __half* __restrict__ wo16, __half* __restrict__ w116,
    __half* __restrict__ w216)
{
    int bb = blockIdx.x;
    const float* in;
    __half* out;
    if (bb < NB_H)            { in = Wo; out = wo16; }
    else if (bb < NB_H + NB_F){ in = W1; out = w116; bb -= NB_H; }
    else                      { in = W2; out = w216; bb -= NB_H + NB_F; }
    int i = (bb * 256 + threadIdx.x) * 4;
    float4 v = *(const float4*)(in + i);
    __half2 pk2[2];
    pk2[0] = __floats2half2_rn(v.x, v.y);
    pk2[1] = __floats2half2_rn(v.z, v.w);
    *(uint2*)(out + i) = *(const uint2*)pk2;
}

// ---------------- Wq|Wv concat convert: out[k][0:1024]=Wq, [1024:2048]=Wv ----
__global__ __launch_bounds__(256) void cvt_qv(
    const float* __restrict__ Wq, const float* __restrict__ Wv,
    const float* __restrict__ bq, const float* __restrict__ bv,
    __half* __restrict__ out, float* __restrict__ bqv)
{
    int i = (blockIdx.x * 256 + threadIdx.x) * 4;   // over HID*HID
    int k = i >> 10, n = i & 1023;
    float4 q = *(const float4*)(Wq + i);
    float4 v = *(const float4*)(Wv + i);
    __half2 pq[2], pv[2];
    pq[0] = __floats2half2_rn(q.x, q.y); pq[1] = __floats2half2_rn(q.z, q.w);
    pv[0] = __floats2half2_rn(v.x, v.y); pv[1] = __floats2half2_rn(v.z, v.w);
    *(uint2*)(out + (size_t)k * QVN + n)        = *(const uint2*)pq;
    *(uint2*)(out + (size_t)k * QVN + 1024 + n) = *(const uint2*)pv;
    if (i < 1024) {     // first 256 threads also copy biases (4 each)
        *(float4*)(bqv + i)        = *(const float4*)(bq + i);
        *(float4*)(bqv + 1024 + i) = *(const float4*)(bv + i);
    }
}

// ---------------- LayerNorm: one block per row, fp16 out ----------------
__global__ __launch_bounds__(256) void ln_kernel(
    const float* __restrict__ x, const float* __restrict__ gamma,
    const float* __restrict__ beta, __half* __restrict__ out)
{
    int row = blockIdx.x;
    int t = threadIdx.x;
    const float4* xr = (const float4*)(x + (size_t)row * HID);
    float4 v = xr[t];
    float s  = v.x + v.y + v.z + v.w;
    float ss = v.x*v.x + v.y*v.y + v.z*v.z + v.w*v.w;
    #pragma unroll
    for (int o = 16; o; o >>= 1) {
        s  += __shfl_xor_sync(0xffffffffu, s,  o);
        ss += __shfl_xor_sync(0xffffffffu, ss, o);
    }
    __shared__ float rs[8], rss[8];
    if ((t & 31) == 0) { rs[t >> 5] = s; rss[t >> 5] = ss; }
    __syncthreads();
    s = 0.f; ss = 0.f;
    #pragma unroll
    for (int i = 0; i < 8; i++) { s += rs[i]; ss += rss[i]; }
    float mu  = s * (1.f / HID);
    float var = ss * (1.f / HID) - mu * mu;
    float inv = rsqrtf(var + 1e-5f);
    float4 g4 = ((const float4*)gamma)[t];
    float4 b4 = ((const float4*)beta)[t];
    __half2 pk2[2];
    pk2[0] = __floats2half2_rn((v.x - mu) * inv * g4.x + b4.x,
                               (v.y - mu) * inv * g4.y + b4.y);
    pk2[1] = __floats2half2_rn((v.z - mu) * inv * g4.z + b4.z,
                               (v.w - mu) * inv * g4.w + b4.w);
    *(uint2*)(out + (size_t)row * HID + t * 4) = *(const uint2*)pk2;
}

// ---------------- GELU (tanh approx, matches reference) ----------------
__device__ __forceinline__ float gelu_f(float x)
{
    float u = 0.7978845608028654f * (x + 0.044715f * x * x * x);
    return 0.5f * x * (1.f + tanhf(u));
}

// ---------------- FP16 MMA m16n8k16, fp32 accumulate ----------------
__device__ __forceinline__ void mma_h(
    float* c, uint32_t a0, uint32_t a1, uint32_t a2, uint32_t a3,
    uint32_t b0, uint32_t b1)
{
    asm volatile(
        "mma.sync.aligned.m16n8k16.row.col.f32.f16.f16.f32 "
        "{%0,%1,%2,%3}, {%4,%5,%6,%7}, {%8,%9}, {%0,%1,%2,%3};"
        : "+f"(c[0]), "+f"(c[1]), "+f"(c[2]), "+f"(c[3])
        : "r"(a0), "r"(a1), "r"(a2), "r"(a3), "r"(b0), "r"(b1));
}

__device__ __forceinline__ void cp16(void* s, const void* g)
{
    unsigned sa = (unsigned)__cvta_generic_to_shared(s);
    asm volatile("cp.async.cg.shared.global [%0], [%1], 16;" :: "r"(sa), "l"(g));
}

__device__ __forceinline__ void ldm_x4(uint32_t* r, const __half* p)
{
    unsigned a = (unsigned)__cvta_generic_to_shared(p);
    asm volatile(
        "ldmatrix.sync.aligned.m8n8.x4.shared.b16 {%0,%1,%2,%3}, [%4];"
        : "=r"(r[0]), "=r"(r[1]), "=r"(r[2]), "=r"(r[3]) : "r"(a));
}

__device__ __forceinline__ void ldm_x4t(uint32_t* r, const __half* p)
{
    unsigned a = (unsigned)__cvta_generic_to_shared(p);
    asm volatile(
        "ldmatrix.sync.aligned.m8n8.x4.trans.shared.b16 {%0,%1,%2,%3}, [%4];"
        : "=r"(r[0]), "=r"(r[1]), "=r"(r[2]), "=r"(r[3]) : "r"(a));
}

__device__ __forceinline__ uint32_t U32(const __half* p)
{
    return *(const uint32_t*)p;
}

__device__ __forceinline__ uint32_t pack_h2(float x, float y)
{
    __half2 h = __floats2half2_rn(x, y);
    return *(const uint32_t*)&h;
}

__device__ __forceinline__ void st2(float* p, float x, float y)
{
    *(float2*)p = make_float2(x, y);
}
__device__ __forceinline__ void st2(__half* p, float x, float y)
{
    *(__half2*)p = __floats2half2_rn(x, y);
}

// ---------------- FP16 GEMM (persistent tiles): C = A @ W + bias ------------
// W native (K,N) row-major. BM=BN=128, BK=64, 3-stage cp.async pipeline.
// Persistent: each block loops over flattened tiles (kills wave quantization).
// EPI: 0 = bias, 1 = bias + residual, 2 = gelu(bias + acc)
#define AS_H  (128 * 72)        // halves per A stage
#define BS_H  (64 * 136)        // halves per B stage
#define STG_H (AS_H + BS_H)     // halves per stage (17920)
#define HG_SMEM (3 * STG_H * 2) // bytes (107520)
template <int EPI, typename OT>
__global__ __launch_bounds__(256, 2) void hgemm(
    int M, int N, int K, int tilesX, int totalTiles,
    const __half* __restrict__ A, const __half* __restrict__ W,
    const float* __restrict__ bias, const float* __restrict__ R,
    OT* __restrict__ C)
{
    extern __shared__ __half hs[];

    int tid  = threadIdx.x;
    int lane = tid & 31, w = tid >> 5;
    int wm = w >> 1, wn = w & 1;
    int g = lane >> 2, tig = lane & 3;
    int NT = K >> 6;

    for (int tile = blockIdx.x; tile < totalTiles; tile += gridDim.x) {
        int bx = tile % tilesX, by = tile / tilesX;
        const __half* Ab = A + (size_t)by * 128 * K;
        const __half* Wb = W + bx * 128;

        auto stage_in = [&](int s, int t) {
            __half* As = hs + s * STG_H;
            __half* Bs = As + AS_H;
            int k0 = t << 6;
            #pragma unroll
            for (int i = 0; i < 4; i++) {
                int c = tid + i * 256;
                int r = c >> 3, col = (c & 7) * 8;
                cp16(As + r * 72 + col, Ab + (size_t)r * K + k0 + col);
            }
            #pragma unroll
            for (int i = 0; i < 4; i++) {
                int c = tid + i * 256;
                int r = c >> 4, col = (c & 15) * 8;
                cp16(Bs + r * 136 + col, Wb + (size_t)(k0 + r) * N + col);
            }
            asm volatile("cp.async.commit_group;");
        };

        float acc[2][8][4] = {};

        stage_in(0, 0);
        stage_in(1, 1);

        int s = 0;
        for (int t = 0; t < NT; t++) {
            asm volatile("cp.async.wait_group 1;");
            __syncthreads();

            if (t + 2 < NT) stage_in((s + 2) % 3, t + 2);
            else            asm volatile("cp.async.commit_group;");

            __half* As = hs + s * STG_H;
            __half* Bs = As + AS_H;

            #pragma unroll
            for (int kk = 0; kk < 4; kk++) {
                int k8 = kk * 16;
                uint32_t a[2][4];
                #pragma unroll
                for (int i = 0; i < 2; i++)
                    ldm_x4(a[i], As + (wm * 32 + i * 16 + (lane & 15)) * 72
                                   + k8 + (lane >> 4) * 8);
                #pragma unroll
                for (int jp = 0; jp < 4; jp++) {
                    uint32_t b[4];
                    ldm_x4t(b, Bs + (k8 + (lane & 15)) * 136
                                 + wn * 64 + jp * 16 + (lane >> 4) * 8);
                    #pragma unroll
                    for (int i = 0; i < 2; i++) {
                        mma_h(acc[i][2 * jp    ], a[i][0], a[i][1], a[i][2],
                              a[i][3], b[0], b[1]);
                        mma_h(acc[i][2 * jp + 1], a[i][0], a[i][1], a[i][2],
                              a[i][3], b[2], b[3]);
                    }
                }
            }
            s = (s + 1) % 3;
        }

        // ---- epilogue ----
        #pragma unroll
        for (int i = 0; i < 2; i++) {
            int r0 = by * 128 + wm * 32 + i * 16 + g;
            int r1 = r0 + 8;
            #pragma unroll
            for (int j = 0; j < 8; j++) {
                int col = bx * 128 + wn * 64 + j * 8 + tig * 2;
                float2 bb = *(const float2*)(bias + col);
                float v00 = acc[i][j][0] + bb.x, v01 = acc[i][j][1] + bb.y;
                float v10 = acc[i][j][2] + bb.x, v11 = acc[i][j][3] + bb.y;
                if (EPI == 1) {
                    float2 q0 = *(const float2*)(R + (size_t)r0 * N + col);
                    float2 q1 = *(const float2*)(R + (size_t)r1 * N + col);
                    v00 += q0.x; v01 += q0.y;
                    v10 += q1.x; v11 += q1.y;
                } else if (EPI == 2) {
                    v00 = gelu_f(v00); v01 = gelu_f(v01);
                    v10 = gelu_f(v10); v11 = gelu_f(v11);
                }
                st2(C + (size_t)r0 * N + col, v00, v01);
                st2(C + (size_t)r1 * N + col, v10, v11);
            }
        }
        __syncthreads();    // all reads of smem done before next tile's stage 0
    }
}

// ---------------- FP16 causal flash attention ---------------------------------
// Register-held P; ldmatrix.x4 K and V fragments; 3-buffer cp.async K/V
// pipeline with ONE __syncthreads per tile iteration.
#define SH 72
#define AT_KV   (64 * SH)                      // halves per K or V buffer
#define AT_SMEM ((6 * AT_KV + 128 * SH) * 2)   // bytes (73728)
__global__ __launch_bounds__(256, 2) void attn_h(
    const __half* __restrict__ QV, __half* __restrict__ O)
{
    extern __shared__ __half sm[];
    __half* KsB = sm;                   // [3][64][SH]
    __half* VsB = sm + 3 * AT_KV;       // [3][64][SH]
    __half* Ps  = sm + 6 * AT_KV;       // [128][SH]  Q staging only

    int qt = (int)gridDim.x - 1 - (int)blockIdx.x;   // longest first
    int bh = blockIdx.y;
    int b = bh >> 4, h = bh & 15;
    int tid = threadIdx.x, lane = tid & 31, w = tid >> 5;
    int g = lane >> 2, tig = lane & 3;
    int m0 = w * 16;
    int lm  = lane >> 3, lmr = lane & 7;    // ldmatrix x4 lane decomposition
    const __half* Qh = QV + (size_t)b * SEQ * QVN + h * DK;
    const __half* Vh = Qh + 1024;
    size_t obase = (size_t)b * SEQ * HID + (size_t)h * DK;

    auto stage_kv = [&](int s, int kt) {
        #pragma unroll
        for (int i = 0; i < 2; i++) {
            int idx = tid + i * 256;            // 64 rows x 8 chunks
            int row = idx >> 3, c8 = (idx & 7) * 8;
            cp16(KsB + s * AT_KV + row * SH + c8,
                 Qh + (size_t)(kt * 64 + row) * QVN + c8);
            cp16(VsB + s * AT_KV + row * SH + c8,
                 Vh + (size_t)(kt * 64 + row) * QVN + c8);
        }
        asm volatile("cp.async.commit_group;");
    };

    int ktmax = 2 * qt + 1;

    // ---- stage Q tile, prefetch k-tiles 0 and 1, lift Q fragments ----
    #pragma unroll
    for (int i = 0; i < 4; i++) {
        int idx = tid + i * 256;
        int row = idx >> 3, c8 = (idx & 7) * 8;
        *(uint4*)&Ps[row * SH + c8] =
            *(const uint4*)(Qh + (size_t)(qt * 128 + row) * QVN + c8);
    }
    stage_kv(0, 0);
    if (1 <= ktmax) stage_kv(1, 1);
    else asm volatile("cp.async.commit_group;");
    __syncthreads();
    uint32_t qf[4][4];
    #pragma unroll
    for (int kg = 0; kg < 4; kg++) {
        qf[kg][0] = U32(&Ps[(m0 + g    ) * SH + kg * 16 + 2 * tig]);
        qf[kg][1] = U32(&Ps[(m0 + g + 8) * SH + kg * 16 + 2 * tig]);
        qf[kg][2] = U32(&Ps[(m0 + g    ) * SH + kg * 16 + 8 + 2 * tig]);
        qf[kg][3] = U32(&Ps[(m0 + g + 8) * SH + kg * 16 + 8 + 2 * tig]);
    }

    float oacc[8][4] = {};
    float mr0 = -INFINITY, mr1 = -INFINITY, l0 = 0.f, l1 = 0.f;
    int r0g = qt * 128 + m0 + g;
    int r1g = r0g + 8;

    for (int kt = 0; kt <= ktmax; kt++) {
        asm volatile("cp.async.wait_group 1;");     // tile kt ready
        __syncthreads();                            // visible; iter kt-1 done
        if (kt + 2 <= ktmax) stage_kv((kt + 2) % 3, kt + 2);
        else asm volatile("cp.async.commit_group;");

        const __half* Ks = KsB + (kt % 3) * AT_KV;
        const __half* Vs = VsB + (kt % 3) * AT_KV;

        // ---- S = Q K^T : K B-fragments via ldmatrix.x4 (j pairs) ----
        float sacc[8][4] = {};
        #pragma unroll
        for (int kg = 0; kg < 4; kg++) {
            #pragma unroll
            for (int jp = 0; jp < 4; jp++) {
                uint32_t bf[4];
                ldm_x4(bf, Ks + (jp * 16 + (lm >> 1) * 8 + lmr) * SH
                             + kg * 16 + (lm & 1) * 8);
                mma_h(sacc[2 * jp    ], qf[kg][0], qf[kg][1], qf[kg][2],
                      qf[kg][3], bf[0], bf[1]);
                mma_h(sacc[2 * jp + 1], qf[kg][0], qf[kg][1], qf[kg][2],
                      qf[kg][3], bf[2], bf[3]);
            }
        }

        // ---- scale + causal mask ----
        const float scale = 0.125f;
        if (kt >= 2 * qt) {
            #pragma unroll
            for (int j = 0; j < 8; j++) {
                int c0 = kt * 64 + j * 8 + 2 * tig;
                sacc[j][0] = (c0     > r0g) ? -INFINITY : sacc[j][0] * scale;
                sacc[j][1] = (c0 + 1 > r0g) ? -INFINITY : sacc[j][1] * scale;
                sacc[j][2] = (c0     > r1g) ? -INFINITY : sacc[j][2] * scale;
                sacc[j][3] = (c0 + 1 > r1g) ? -INFINITY : sacc[j][3] * scale;
            }
        } else {
            #pragma unroll
            for (int j = 0; j < 8; j++)
                #pragma unroll
                for (int c = 0; c < 4; c++) sacc[j][c] *= scale;
        }

        // ---- online softmax (fp32) ----
        float mt0 = mr0, mt1 = mr1;
        #pragma unroll
        for (int j = 0; j < 8; j++) {
            mt0 = fmaxf(mt0, fmaxf(sacc[j][0], sacc[j][1]));
            mt1 = fmaxf(mt1, fmaxf(sacc[j][2], sacc[j][3]));
        }
        mt0 = fmaxf(mt0, __shfl_xor_sync(0xffffffffu, mt0, 1));
        mt0 = fmaxf(mt0, __shfl_xor_sync(0xffffffffu, mt0, 2));
        mt1 = fmaxf(mt1, __shfl_xor_sync(0xffffffffu, mt1, 1));
        mt1 = fmaxf(mt1, __shfl_xor_sync(0xffffffffu, mt1, 2));
        float alpha0 = __expf(mr0 - mt0);
        float alpha1 = __expf(mr1 - mt1);
        mr0 = mt0; mr1 = mt1;
        float ps0 = 0.f, ps1 = 0.f;
        #pragma unroll
        for (int j = 0; j < 8; j++) {
            sacc[j][0] = __expf(sacc[j][0] - mt0); ps0 += sacc[j][0];
            sacc[j][1] = __expf(sacc[j][1] - mt0); ps0 += sacc[j][1];
            sacc[j][2] = __expf(sacc[j][2] - mt1); ps1 += sacc[j][2];
            sacc[j][3] = __expf(sacc[j][3] - mt1); ps1 += sacc[j][3];
        }
        ps0 += __shfl_xor_sync(0xffffffffu, ps0, 1);
        ps0 += __shfl_xor_sync(0xffffffffu, ps0, 2);
        ps1 += __shfl_xor_sync(0xffffffffu, ps1, 1);
        ps1 += __shfl_xor_sync(0xffffffffu, ps1, 2);
        l0 = l0 * alpha0 + ps0;
        l1 = l1 * alpha1 + ps1;
        #pragma unroll
        for (int j = 0; j < 8; j++) {
            oacc[j][0] *= alpha0; oacc[j][1] *= alpha0;
            oacc[j][2] *= alpha1; oacc[j][3] *= alpha1;
        }

        // ---- O += P V : register P, V fragments via ldmatrix.x4.trans ------
        #pragma unroll
        for (int kp = 0; kp < 4; kp++) {
            uint32_t a0 = pack_h2(sacc[2 * kp    ][0], sacc[2 * kp    ][1]);
            uint32_t a1 = pack_h2(sacc[2 * kp    ][2], sacc[2 * kp    ][3]);
            uint32_t a2 = pack_h2(sacc[2 * kp + 1][0], sacc[2 * kp + 1][1]);
            uint32_t a3 = pack_h2(sacc[2 * kp + 1][2], sacc[2 * kp + 1][3]);
            #pragma unroll
            for (int jp = 0; jp < 4; jp++) {
                uint32_t bf[4];
                ldm_x4t(bf, Vs + (kp * 16 + (lm & 1) * 8 + lmr) * SH
                              + (2 * jp + (lm >> 1)) * 8);
                mma_h(oacc[2 * jp    ], a0, a1, a2, a3, bf[0], bf[1]);
                mma_h(oacc[2 * jp + 1], a0, a1, a2, a3, bf[2], bf[3]);
            }
        }
    }

    // ---- normalize + write fp16 ----
    float inv0 = 1.f / l0, inv1 = 1.f / l1;
    #pragma unroll
    for (int j = 0; j < 8; j++) {
        int col = j * 8 + 2 * tig;
        *(__half2*)(O + obase + (size_t)r0g * HID + col) =
            __floats2half2_rn(oacc[j][0] * inv0, oacc[j][1] * inv0);
        *(__half2*)(O + obase + (size_t)r1g * HID + col) =
            __floats2half2_rn(oacc[j][2] * inv1, oacc[j][3] * inv1);
    }
}

// ---------------- launch ----------------
extern "C" void kernel_launch(void* const* d_in, const int* in_sizes, int n_in,
                              void* d_out, int out_size)
{
    const float* x     = (const float*)d_in[0];
    const float* Wq    = (const float*)d_in[1];
    const float* bq    = (const float*)d_in[2];
    const float* Wv    = (const float*)d_in[3];
    const float* bv    = (const float*)d_in[4];
    const float* Wo    = (const float*)d_in[5];
    const float* bo    = (const float*)d_in[6];
    const float* W1    = (const float*)d_in[7];
    const float* b1    = (const float*)d_in[8];
    const float* W2    = (const float*)d_in[9];
    const float* b2    = (const float*)d_in[10];
    const float* g1    = (const float*)d_in[11];
    const float* beta1 = (const float*)d_in[12];
    const float* g2    = (const float*)d_in[13];
    const float* beta2 = (const float*)d_in[14];
    float* out = (float*)d_out;

    float *x1, *bqv;
    __half *qv16, *ln16, *ctx16, *h116, *wqv16, *wo16, *w116, *w216;
    cudaGetSymbolAddress((void**)&x1,    g_x1);
    cudaGetSymbolAddress((void**)&bqv,   g_bqv);
    cudaGetSymbolAddress((void**)&qv16,  g_qv16);
    cudaGetSymbolAddress((void**)&ln16,  g_ln16);
    cudaGetSymbolAddress((void**)&ctx16, g_ctx16);
    cudaGetSymbolAddress((void**)&h116,  g_h116);
    cudaGetSymbolAddress((void**)&wqv16, g_wqv16);
    cudaGetSymbolAddress((void**)&wo16,  g_wo16);
    cudaGetSymbolAddress((void**)&w116,  g_w116);
    cudaGetSymbolAddress((void**)&w216,  g_w216);

    cudaFuncSetAttribute(hgemm<0, __half>,
        cudaFuncAttributeMaxDynamicSharedMemorySize, HG_SMEM);
    cudaFuncSetAttribute(hgemm<1, float>,
        cudaFuncAttributeMaxDynamicSharedMemorySize, HG_SMEM);
    cudaFuncSetAttribute(hgemm<2, __half>,
        cudaFuncAttributeMaxDynamicSharedMemorySize, HG_SMEM);
    cudaFuncSetAttribute(attn_h,
        cudaFuncAttributeMaxDynamicSharedMemorySize, AT_SMEM);

    // weights: fp32 -> fp16 (Wq|Wv concatenated; Wo/W1/W2 fused launch)
    int nh = HID * HID;
    cvt_qv<<<nh / 1024, 256>>>(Wq, Wv, bq, bv, wqv16, bqv);
    cvt_all<<<NB_H + 2 * NB_F, 256>>>(Wo, W1, W2, wo16, w116, w216);

    const int PGRID = 296;      // 2 blocks/SM x 148 SMs
    dim3 blk(256);

    auto pg = [&](int tiles) { return tiles < PGRID ? tiles : PGRID; };
    int tQV = (QVN / 128) * (TOKENS / 128);     // 512
    int tH  = (HID / 128) * (TOKENS / 128);     // 256
    int tFF = (FFDIM / 128) * (TOKENS / 128);   // 1024

    // ln16 = LN(x)
    ln_kernel<<<TOKENS, blk>>>(x, g1, beta1, ln16);
    // qv = ln16 @ [Wq|Wv] + [bq|bv]
    hgemm<0, __half><<<pg(tQV), blk, HG_SMEM>>>(
        TOKENS, QVN, HID, QVN / 128, tQV, ln16, wqv16, bqv, nullptr, qv16);
    // causal attention (Q == K)
    attn_h<<<dim3(SEQ / 128, 2 * NHEADS), blk, AT_SMEM>>>(qv16, ctx16);
    // x1 = x + ctx @ Wo + bo
    hgemm<1, float><<<pg(tH), blk, HG_SMEM>>>(
        TOKENS, HID, HID, HID / 128, tH, ctx16, wo16, bo, x, x1);
    // ln16 = LN(x1)
    ln_kernel<<<TOKENS, blk>>>(x1, g2, beta2, ln16);
    // h1 = gelu(ln16 @ W1 + b1), fp16 out
    hgemm<2, __half><<<pg(tFF), blk, HG_SMEM>>>(
        TOKENS, FFDIM, HID, FFDIM / 128, tFF, ln16, w116, b1, nullptr, h116);
    // out = x1 + h1 @ W2 + b2
    hgemm<1, float><<<pg(tH), blk, HG_SMEM>>>(
        TOKENS, HID, FFDIM, HID / 128, tH, h116, w216, b2, x1, out);
}

// round 15
// speedup vs baseline: 1.0311x; 1.0311x over previous
#include <cuda_runtime.h>
#include <cuda_fp16.h>
#include <math.h>
#include <stdint.h>

#define TOKENS 4096      // 2 * 2048
#define HID    1024
#define FFDIM  4096
#define SEQ    2048
#define NHEADS 16
#define DK     64
#define QVN    2048      // fused Q|V projection width

// ---------------- scratch (device globals; no allocs allowed) ----------------
__device__ float  g_x1  [TOKENS * HID];
__device__ __half g_qv16[(size_t)TOKENS * QVN];
__device__ __half g_ln16[TOKENS * HID];
__device__ __half g_ctx16[TOKENS * HID];
__device__ __half g_h116[(size_t)TOKENS * FFDIM];
// fp16 weights
__device__ __half g_wqv16[(size_t)HID * QVN];   // [k][ Wq | Wv ]
__device__ __half g_wo16[HID * HID];
__device__ __half g_w116[(size_t)HID * FFDIM];
__device__ __half g_w216[(size_t)HID * FFDIM];
__device__ float  g_bqv [QVN];

// ---------------- fused weight convert: Wo + W1 + W2 in ONE launch ----------
#define NB_H (HID * HID / 1024)
#define NB_F (HID * FFDIM / 1024)
__global__ __launch_bounds__(256) void cvt_all(
    const float* __restrict__ Wo, const float* __restrict__ W1,
    const float* __restrict__ W2,
    __half* __restrict__ wo16, __half* __restrict__ w116,
    __half* __restrict__ w216)
{
    int bb = blockIdx.x;
    const float* in;
    __half* out;
    if (bb < NB_H)            { in = Wo; out = wo16; }
    else if (bb < NB_H + NB_F){ in = W1; out = w116; bb -= NB_H; }
    else                      { in = W2; out = w216; bb -= NB_H + NB_F; }
    int i = (bb * 256 + threadIdx.x) * 4;
    float4 v = *(const float4*)(in + i);
    __half2 pk2[2];
    pk2[0] = __floats2half2_rn(v.x, v.y);
    pk2[1] = __floats2half2_rn(v.z, v.w);
    *(uint2*)(out + i) = *(const uint2*)pk2;
}

// ---------------- Wq|Wv concat convert: out[k][0:1024]=Wq, [1024:2048]=Wv ----
__global__ __launch_bounds__(256) void cvt_qv(
    const float* __restrict__ Wq, const float* __restrict__ Wv,
    const float* __restrict__ bq, const float* __restrict__ bv,
    __half* __restrict__ out, float* __restrict__ bqv)
{
    int i = (blockIdx.x * 256 + threadIdx.x) * 4;   // over HID*HID
    int k = i >> 10, n = i & 1023;
    float4 q = *(const float4*)(Wq + i);
    float4 v = *(const float4*)(Wv + i);
    __half2 pq[2], pv[2];
    pq[0] = __floats2half2_rn(q.x, q.y); pq[1] = __floats2half2_rn(q.z, q.w);
    pv[0] = __floats2half2_rn(v.x, v.y); pv[1] = __floats2half2_rn(v.z, v.w);
    *(uint2*)(out + (size_t)k * QVN + n)        = *(const uint2*)pq;
    *(uint2*)(out + (size_t)k * QVN + 1024 + n) = *(const uint2*)pv;
    if (i < 1024) {     // first 256 threads also copy biases (4 each)
        *(float4*)(bqv + i)        = *(const float4*)(bq + i);
        *(float4*)(bqv + 1024 + i) = *(const float4*)(bv + i);
    }
}

// ---------------- LayerNorm: one block per row, fp16 out ----------------
__global__ __launch_bounds__(256) void ln_kernel(
    const float* __restrict__ x, const float* __restrict__ gamma,
    const float* __restrict__ beta, __half* __restrict__ out)
{
    int row = blockIdx.x;
    int t = threadIdx.x;
    const float4* xr = (const float4*)(x + (size_t)row * HID);
    float4 v = xr[t];
    float s  = v.x + v.y + v.z + v.w;
    float ss = v.x*v.x + v.y*v.y + v.z*v.z + v.w*v.w;
    #pragma unroll
    for (int o = 16; o; o >>= 1) {
        s  += __shfl_xor_sync(0xffffffffu, s,  o);
        ss += __shfl_xor_sync(0xffffffffu, ss, o);
    }
    __shared__ float rs[8], rss[8];
    if ((t & 31) == 0) { rs[t >> 5] = s; rss[t >> 5] = ss; }
    __syncthreads();
    s = 0.f; ss = 0.f;
    #pragma unroll
    for (int i = 0; i < 8; i++) { s += rs[i]; ss += rss[i]; }
    float mu  = s * (1.f / HID);
    float var = ss * (1.f / HID) - mu * mu;
    float inv = rsqrtf(var + 1e-5f);
    float4 g4 = ((const float4*)gamma)[t];
    float4 b4 = ((const float4*)beta)[t];
    __half2 pk2[2];
    pk2[0] = __floats2half2_rn((v.x - mu) * inv * g4.x + b4.x,
                               (v.y - mu) * inv * g4.y + b4.y);
    pk2[1] = __floats2half2_rn((v.z - mu) * inv * g4.z + b4.z,
                               (v.w - mu) * inv * g4.w + b4.w);
    *(uint2*)(out + (size_t)row * HID + t * 4) = *(const uint2*)pk2;
}

// ---------------- GELU (tanh approx, matches reference) ----------------
__device__ __forceinline__ float gelu_f(float x)
{
    float u = 0.7978845608028654f * (x + 0.044715f * x * x * x);
    return 0.5f * x * (1.f + tanhf(u));
}

// ---------------- FP16 MMA m16n8k16, fp32 accumulate ----------------
__device__ __forceinline__ void mma_h(
    float* c, uint32_t a0, uint32_t a1, uint32_t a2, uint32_t a3,
    uint32_t b0, uint32_t b1)
{
    asm volatile(
        "mma.sync.aligned.m16n8k16.row.col.f32.f16.f16.f32 "
        "{%0,%1,%2,%3}, {%4,%5,%6,%7}, {%8,%9}, {%0,%1,%2,%3};"
        : "+f"(c[0]), "+f"(c[1]), "+f"(c[2]), "+f"(c[3])
        : "r"(a0), "r"(a1), "r"(a2), "r"(a3), "r"(b0), "r"(b1));
}

__device__ __forceinline__ void cp16(void* s, const void* g)
{
    unsigned sa = (unsigned)__cvta_generic_to_shared(s);
    asm volatile("cp.async.cg.shared.global [%0], [%1], 16;" :: "r"(sa), "l"(g));
}

__device__ __forceinline__ void ldm_x4(uint32_t* r, const __half* p)
{
    unsigned a = (unsigned)__cvta_generic_to_shared(p);
    asm volatile(
        "ldmatrix.sync.aligned.m8n8.x4.shared.b16 {%0,%1,%2,%3}, [%4];"
        : "=r"(r[0]), "=r"(r[1]), "=r"(r[2]), "=r"(r[3]) : "r"(a));
}

__device__ __forceinline__ void ldm_x4t(uint32_t* r, const __half* p)
{
    unsigned a = (unsigned)__cvta_generic_to_shared(p);
    asm volatile(
        "ldmatrix.sync.aligned.m8n8.x4.trans.shared.b16 {%0,%1,%2,%3}, [%4];"
        : "=r"(r[0]), "=r"(r[1]), "=r"(r[2]), "=r"(r[3]) : "r"(a));
}

__device__ __forceinline__ uint32_t U32(const __half* p)
{
    return *(const uint32_t*)p;
}

__device__ __forceinline__ uint32_t pack_h2(float x, float y)
{
    __half2 h = __floats2half2_rn(x, y);
    return *(const uint32_t*)&h;
}

__device__ __forceinline__ void st2(float* p, float x, float y)
{
    *(float2*)p = make_float2(x, y);
}
__device__ __forceinline__ void st2(__half* p, float x, float y)
{
    *(__half2*)p = __floats2half2_rn(x, y);
}

// ---------------- FP16 GEMM: C = A(MxK) @ W(KxN) + bias (+res / gelu) ------
// W in native (K,N) row-major. BM=BN=128, BK=64, 3-stage cp.async pipeline.
// Fragment loads batched per k-step: all 6 ldmatrix issued before the 16 mmas
// (exposes 6 concurrent LDS round-trips instead of serial load->mma chains).
// EPI: 0 = bias, 1 = bias + residual, 2 = gelu(bias + acc)
#define AS_H  (128 * 72)        // halves per A stage
#define BS_H  (64 * 136)        // halves per B stage
#define STG_H (AS_H + BS_H)     // halves per stage (17920)
#define HG_SMEM (3 * STG_H * 2) // bytes (107520)
template <int EPI, typename OT>
__global__ __launch_bounds__(256, 2) void hgemm(
    int M, int N, int K,
    const __half* __restrict__ A, const __half* __restrict__ W,
    const float* __restrict__ bias, const float* __restrict__ R,
    OT* __restrict__ C)
{
    extern __shared__ __half hs[];

    int tid  = threadIdx.x;
    int lane = tid & 31, w = tid >> 5;
    int wm = w >> 1, wn = w & 1;
    int g = lane >> 2, tig = lane & 3;
    int bx = blockIdx.x, by = blockIdx.y;

    const __half* Ab = A + (size_t)by * 128 * K;
    const __half* Wb = W + bx * 128;

    auto stage_in = [&](int s, int t) {
        __half* As = hs + s * STG_H;
        __half* Bs = As + AS_H;
        int k0 = t << 6;
        #pragma unroll
        for (int i = 0; i < 4; i++) {
            int c = tid + i * 256;
            int r = c >> 3, col = (c & 7) * 8;
            cp16(As + r * 72 + col, Ab + (size_t)r * K + k0 + col);
        }
        #pragma unroll
        for (int i = 0; i < 4; i++) {
            int c = tid + i * 256;
            int r = c >> 4, col = (c & 15) * 8;
            cp16(Bs + r * 136 + col, Wb + (size_t)(k0 + r) * N + col);
        }
        asm volatile("cp.async.commit_group;");
    };

    float acc[2][8][4] = {};
    int NT = K >> 6;

    stage_in(0, 0);
    stage_in(1, 1);

    int s = 0;
    for (int t = 0; t < NT; t++) {
        asm volatile("cp.async.wait_group 1;");
        __syncthreads();

        if (t + 2 < NT) stage_in((s + 2) % 3, t + 2);
        else            asm volatile("cp.async.commit_group;");

        __half* As = hs + s * STG_H;
        __half* Bs = As + AS_H;

        #pragma unroll
        for (int kk = 0; kk < 4; kk++) {
            int k8 = kk * 16;
            // batch ALL fragment loads first (6 ldmatrix, independent)
            uint32_t a[2][4], b[4][4];
            #pragma unroll
            for (int i = 0; i < 2; i++)
                ldm_x4(a[i], As + (wm * 32 + i * 16 + (lane & 15)) * 72
                               + k8 + (lane >> 4) * 8);
            #pragma unroll
            for (int jp = 0; jp < 4; jp++)
                ldm_x4t(b[jp], Bs + (k8 + (lane & 15)) * 136
                                 + wn * 64 + jp * 16 + (lane >> 4) * 8);
            // then the 16 mmas
            #pragma unroll
            for (int jp = 0; jp < 4; jp++) {
                #pragma unroll
                for (int i = 0; i < 2; i++) {
                    mma_h(acc[i][2 * jp    ], a[i][0], a[i][1], a[i][2],
                          a[i][3], b[jp][0], b[jp][1]);
                    mma_h(acc[i][2 * jp + 1], a[i][0], a[i][1], a[i][2],
                          a[i][3], b[jp][2], b[jp][3]);
                }
            }
        }
        s = (s + 1) % 3;
    }

    // ---- epilogue ----
    #pragma unroll
    for (int i = 0; i < 2; i++) {
        int r0 = by * 128 + wm * 32 + i * 16 + g;
        int r1 = r0 + 8;
        #pragma unroll
        for (int j = 0; j < 8; j++) {
            int col = bx * 128 + wn * 64 + j * 8 + tig * 2;
            float2 bb = *(const float2*)(bias + col);
            float v00 = acc[i][j][0] + bb.x, v01 = acc[i][j][1] + bb.y;
            float v10 = acc[i][j][2] + bb.x, v11 = acc[i][j][3] + bb.y;
            if (EPI == 1) {
                float2 q0 = *(const float2*)(R + (size_t)r0 * N + col);
                float2 q1 = *(const float2*)(R + (size_t)r1 * N + col);
                v00 += q0.x; v01 += q0.y;
                v10 += q1.x; v11 += q1.y;
            } else if (EPI == 2) {
                v00 = gelu_f(v00); v01 = gelu_f(v01);
                v10 = gelu_f(v10); v11 = gelu_f(v11);
            }
            st2(C + (size_t)r0 * N + col, v00, v01);
            st2(C + (size_t)r1 * N + col, v10, v11);
        }
    }
}

// ---------------- FP16 causal flash attention ---------------------------------
// Register-held P; ldmatrix.x4 K and V fragments; 3-buffer cp.async K/V
// pipeline with ONE __syncthreads per tile iteration.
#define SH 72
#define AT_KV   (64 * SH)                      // halves per K or V buffer
#define AT_SMEM ((6 * AT_KV + 128 * SH) * 2)   // bytes (73728)
__global__ __launch_bounds__(256, 2) void attn_h(
    const __half* __restrict__ QV, __half* __restrict__ O)
{
    extern __shared__ __half sm[];
    __half* KsB = sm;                   // [3][64][SH]
    __half* VsB = sm + 3 * AT_KV;       // [3][64][SH]
    __half* Ps  = sm + 6 * AT_KV;       // [128][SH]  Q staging only

    int qt = (int)gridDim.x - 1 - (int)blockIdx.x;   // longest first
    int bh = blockIdx.y;
    int b = bh >> 4, h = bh & 15;
    int tid = threadIdx.x, lane = tid & 31, w = tid >> 5;
    int g = lane >> 2, tig = lane & 3;
    int m0 = w * 16;
    int lm  = lane >> 3, lmr = lane & 7;    // ldmatrix x4 lane decomposition
    const __half* Qh = QV + (size_t)b * SEQ * QVN + h * DK;
    const __half* Vh = Qh + 1024;
    size_t obase = (size_t)b * SEQ * HID + (size_t)h * DK;

    auto stage_kv = [&](int s, int kt) {
        #pragma unroll
        for (int i = 0; i < 2; i++) {
            int idx = tid + i * 256;            // 64 rows x 8 chunks
            int row = idx >> 3, c8 = (idx & 7) * 8;
            cp16(KsB + s * AT_KV + row * SH + c8,
                 Qh + (size_t)(kt * 64 + row) * QVN + c8);
            cp16(VsB + s * AT_KV + row * SH + c8,
                 Vh + (size_t)(kt * 64 + row) * QVN + c8);
        }
        asm volatile("cp.async.commit_group;");
    };

    int ktmax = 2 * qt + 1;

    // ---- stage Q tile, prefetch k-tiles 0 and 1, lift Q fragments ----
    #pragma unroll
    for (int i = 0; i < 4; i++) {
        int idx = tid + i * 256;
        int row = idx >> 3, c8 = (idx & 7) * 8;
        *(uint4*)&Ps[row * SH + c8] =
            *(const uint4*)(Qh + (size_t)(qt * 128 + row) * QVN + c8);
    }
    stage_kv(0, 0);
    if (1 <= ktmax) stage_kv(1, 1);
    else asm volatile("cp.async.commit_group;");
    __syncthreads();
    uint32_t qf[4][4];
    #pragma unroll
    for (int kg = 0; kg < 4; kg++) {
        qf[kg][0] = U32(&Ps[(m0 + g    ) * SH + kg * 16 + 2 * tig]);
        qf[kg][1] = U32(&Ps[(m0 + g + 8) * SH + kg * 16 + 2 * tig]);
        qf[kg][2] = U32(&Ps[(m0 + g    ) * SH + kg * 16 + 8 + 2 * tig]);
        qf[kg][3] = U32(&Ps[(m0 + g + 8) * SH + kg * 16 + 8 + 2 * tig]);
    }

    float oacc[8][4] = {};
    float mr0 = -INFINITY, mr1 = -INFINITY, l0 = 0.f, l1 = 0.f;
    int r0g = qt * 128 + m0 + g;
    int r1g = r0g + 8;

    for (int kt = 0; kt <= ktmax; kt++) {
        asm volatile("cp.async.wait_group 1;");     // tile kt ready
        __syncthreads();                            // visible; iter kt-1 done
        if (kt + 2 <= ktmax) stage_kv((kt + 2) % 3, kt + 2);
        else asm volatile("cp.async.commit_group;");

        const __half* Ks = KsB + (kt % 3) * AT_KV;
        const __half* Vs = VsB + (kt % 3) * AT_KV;

        // ---- S = Q K^T : K B-fragments via ldmatrix.x4 (j pairs) ----
        float sacc[8][4] = {};
        #pragma unroll
        for (int kg = 0; kg < 4; kg++) {
            uint32_t bf[4][4];
            #pragma unroll
            for (int jp = 0; jp < 4; jp++)
                ldm_x4(bf[jp], Ks + (jp * 16 + (lm >> 1) * 8 + lmr) * SH
                                 + kg * 16 + (lm & 1) * 8);
            #pragma unroll
            for (int jp = 0; jp < 4; jp++) {
                mma_h(sacc[2 * jp    ], qf[kg][0], qf[kg][1], qf[kg][2],
                      qf[kg][3], bf[jp][0], bf[jp][1]);
                mma_h(sacc[2 * jp + 1], qf[kg][0], qf[kg][1], qf[kg][2],
                      qf[kg][3], bf[jp][2], bf[jp][3]);
            }
        }

        // ---- scale + causal mask ----
        const float scale = 0.125f;
        if (kt >= 2 * qt) {
            #pragma unroll
            for (int j = 0; j < 8; j++) {
                int c0 = kt * 64 + j * 8 + 2 * tig;
                sacc[j][0] = (c0     > r0g) ? -INFINITY : sacc[j][0] * scale;
                sacc[j][1] = (c0 + 1 > r0g) ? -INFINITY : sacc[j][1] * scale;
                sacc[j][2] = (c0     > r1g) ? -INFINITY : sacc[j][2] * scale;
                sacc[j][3] = (c0 + 1 > r1g) ? -INFINITY : sacc[j][3] * scale;
            }
        } else {
            #pragma unroll
            for (int j = 0; j < 8; j++)
                #pragma unroll
                for (int c = 0; c < 4; c++) sacc[j][c] *= scale;
        }

        // ---- online softmax (fp32) ----
        float mt0 = mr0, mt1 = mr1;
        #pragma unroll
        for (int j = 0; j < 8; j++) {
            mt0 = fmaxf(mt0, fmaxf(sacc[j][0], sacc[j][1]));
            mt1 = fmaxf(mt1, fmaxf(sacc[j][2], sacc[j][3]));
        }
        mt0 = fmaxf(mt0, __shfl_xor_sync(0xffffffffu, mt0, 1));
        mt0 = fmaxf(mt0, __shfl_xor_sync(0xffffffffu, mt0, 2));
        mt1 = fmaxf(mt1, __shfl_xor_sync(0xffffffffu, mt1, 1));
        mt1 = fmaxf(mt1, __shfl_xor_sync(0xffffffffu, mt1, 2));
        float alpha0 = __expf(mr0 - mt0);
        float alpha1 = __expf(mr1 - mt1);
        mr0 = mt0; mr1 = mt1;
        float ps0 = 0.f, ps1 = 0.f;
        #pragma unroll
        for (int j = 0; j < 8; j++) {
            sacc[j][0] = __expf(sacc[j][0] - mt0); ps0 += sacc[j][0];
            sacc[j][1] = __expf(sacc[j][1] - mt0); ps0 += sacc[j][1];
            sacc[j][2] = __expf(sacc[j][2] - mt1); ps1 += sacc[j][2];
            sacc[j][3] = __expf(sacc[j][3] - mt1); ps1 += sacc[j][3];
        }
        ps0 += __shfl_xor_sync(0xffffffffu, ps0, 1);
        ps0 += __shfl_xor_sync(0xffffffffu, ps0, 2);
        ps1 += __shfl_xor_sync(0xffffffffu, ps1, 1);
        ps1 += __shfl_xor_sync(0xffffffffu, ps1, 2);
        l0 = l0 * alpha0 + ps0;
        l1 = l1 * alpha1 + ps1;
        #pragma unroll
        for (int j = 0; j < 8; j++) {
            oacc[j][0] *= alpha0; oacc[j][1] *= alpha0;
            oacc[j][2] *= alpha1; oacc[j][3] *= alpha1;
        }

        // ---- O += P V : register P, V fragments via ldmatrix.x4.trans ------
        #pragma unroll
        for (int kp = 0; kp < 4; kp++) {
            uint32_t a0 = pack_h2(sacc[2 * kp    ][0], sacc[2 * kp    ][1]);
            uint32_t a1 = pack_h2(sacc[2 * kp    ][2], sacc[2 * kp    ][3]);
            uint32_t a2 = pack_h2(sacc[2 * kp + 1][0], sacc[2 * kp + 1][1]);
            uint32_t a3 = pack_h2(sacc[2 * kp + 1][2], sacc[2 * kp + 1][3]);
            uint32_t bf[4][4];
            #pragma unroll
            for (int jp = 0; jp < 4; jp++)
                ldm_x4t(bf[jp], Vs + (kp * 16 + (lm & 1) * 8 + lmr) * SH
                                  + (2 * jp + (lm >> 1)) * 8);
            #pragma unroll
            for (int jp = 0; jp < 4; jp++) {
                mma_h(oacc[2 * jp    ], a0, a1, a2, a3, bf[jp][0], bf[jp][1]);
                mma_h(oacc[2 * jp + 1], a0, a1, a2, a3, bf[jp][2], bf[jp][3]);
            }
        }
    }

    // ---- normalize + write fp16 ----
    float inv0 = 1.f / l0, inv1 = 1.f / l1;
    #pragma unroll
    for (int j = 0; j < 8; j++) {
        int col = j * 8 + 2 * tig;
        *(__half2*)(O + obase + (size_t)r0g * HID + col) =
            __floats2half2_rn(oacc[j][0] * inv0, oacc[j][1] * inv0);
        *(__half2*)(O + obase + (size_t)r1g * HID + col) =
            __floats2half2_rn(oacc[j][2] * inv1, oacc[j][3] * inv1);
    }
}

// ---------------- launch ----------------
extern "C" void kernel_launch(void* const* d_in, const int* in_sizes, int n_in,
                              void* d_out, int out_size)
{
    const float* x     = (const float*)d_in[0];
    const float* Wq    = (const float*)d_in[1];
    const float* bq    = (const float*)d_in[2];
    const float* Wv    = (const float*)d_in[3];
    const float* bv    = (const float*)d_in[4];
    const float* Wo    = (const float*)d_in[5];
    const float* bo    = (const float*)d_in[6];
    const float* W1    = (const float*)d_in[7];
    const float* b1    = (const float*)d_in[8];
    const float* W2    = (const float*)d_in[9];
    const float* b2    = (const float*)d_in[10];
    const float* g1    = (const float*)d_in[11];
    const float* beta1 = (const float*)d_in[12];
    const float* g2    = (const float*)d_in[13];
    const float* beta2 = (const float*)d_in[14];
    float* out = (float*)d_out;

    float *x1, *bqv;
    __half *qv16, *ln16, *ctx16, *h116, *wqv16, *wo16, *w116, *w216;
    cudaGetSymbolAddress((void**)&x1,    g_x1);
    cudaGetSymbolAddress((void**)&bqv,   g_bqv);
    cudaGetSymbolAddress((void**)&qv16,  g_qv16);
    cudaGetSymbolAddress((void**)&ln16,  g_ln16);
    cudaGetSymbolAddress((void**)&ctx16, g_ctx16);
    cudaGetSymbolAddress((void**)&h116,  g_h116);
    cudaGetSymbolAddress((void**)&wqv16, g_wqv16);
    cudaGetSymbolAddress((void**)&wo16,  g_wo16);
    cudaGetSymbolAddress((void**)&w116,  g_w116);
    cudaGetSymbolAddress((void**)&w216,  g_w216);

    cudaFuncSetAttribute(hgemm<0, __half>,
        cudaFuncAttributeMaxDynamicSharedMemorySize, HG_SMEM);
    cudaFuncSetAttribute(hgemm<1, float>,
        cudaFuncAttributeMaxDynamicSharedMemorySize, HG_SMEM);
    cudaFuncSetAttribute(hgemm<2, __half>,
        cudaFuncAttributeMaxDynamicSharedMemorySize, HG_SMEM);
    cudaFuncSetAttribute(attn_h,
        cudaFuncAttributeMaxDynamicSharedMemorySize, AT_SMEM);

    // weights: fp32 -> fp16 (Wq|Wv concatenated; Wo/W1/W2 fused launch)
    int nh = HID * HID;
    cvt_qv<<<nh / 1024, 256>>>(Wq, Wv, bq, bv, wqv16, bqv);
    cvt_all<<<NB_H + 2 * NB_F, 256>>>(Wo, W1, W2, wo16, w116, w216);

    dim3 blk(256);
    dim3 gHID(HID / 128, TOKENS / 128);     // (8, 32)
    dim3 gQV (QVN / 128, TOKENS / 128);     // (16, 32)
    dim3 gFF (FFDIM / 128, TOKENS / 128);   // (32, 32)

    // ln16 = LN(x)
    ln_kernel<<<TOKENS, blk>>>(x, g1, beta1, ln16);
    // qv = ln16 @ [Wq|Wv] + [bq|bv]
    hgemm<0, __half><<<gQV, blk, HG_SMEM>>>(TOKENS, QVN, HID, ln16, wqv16, bqv, nullptr, qv16);
    // causal attention (Q == K)
    attn_h<<<dim3(SEQ / 128, 2 * NHEADS), blk, AT_SMEM>>>(qv16, ctx16);
    // x1 = x + ctx @ Wo + bo
    hgemm<1, float><<<gHID, blk, HG_SMEM>>>(TOKENS, HID, HID, ctx16, wo16, bo, x, x1);
    // ln16 = LN(x1)
    ln_kernel<<<TOKENS, blk>>>(x1, g2, beta2, ln16);
    // h1 = gelu(ln16 @ W1 + b1), fp16 out
    hgemm<2, __half><<<gFF, blk, HG_SMEM>>>(TOKENS, FFDIM, HID, ln16, w116, b1, nullptr, h116);
    // out = x1 + h1 @ W2 + b2
    hgemm<1, float><<<gHID, blk, HG_SMEM>>>(TOKENS, HID, FFDIM, h116, w216, b2, x1, out);
}